// round 2
// baseline (speedup 1.0000x reference)
#include <cuda_runtime.h>

// Problem dims
#define T_DIM 32
#define B_DIM 64
#define D_DIM 256
#define P_DIM 1024
#define M_TOT (T_DIM * B_DIM)   // 2048
#define KNOTS 17

// GEMM tiling
#define BM 128
#define BN 64
#define BK 16

// Scratch (static device globals — no runtime allocation)
__device__ float g_x[M_TOT * P_DIM];     // 8 MB: projections x[t*B+b][p]
__device__ float g_inv[P_DIM];           // 1/||A_col||
__device__ float g_partial[512];         // block partials from trig kernel

// ---- Packed f32x2 helpers (Blackwell; PTX-only) -----------------------------
#define FMA_F32X2(d, a, b, c) \
    asm("fma.rn.f32x2 %0, %1, %2, %3;" : "=l"(d) : "l"(a), "l"(b), "l"(c))
#define ADD_F32X2_(d, a, b) \
    asm("add.rn.f32x2 %0, %1, %2;" : "=l"(d) : "l"(a), "l"(b))
#define PACK2(d, lo, hi) \
    asm("mov.b64 %0, {%1, %2};" : "=l"(d) : "r"(__float_as_uint(lo)), "r"(__float_as_uint(hi)))
#define UNPACK2(lo, hi, s) \
    do { unsigned _l, _h; \
         asm("mov.b64 {%0, %1}, %2;" : "=r"(_l), "=r"(_h) : "l"(s)); \
         lo = __uint_as_float(_l); hi = __uint_as_float(_h); } while (0)

typedef unsigned long long u64;

// ---------------------------------------------------------------------------
// Kernel 0: column inverse norms of A.  1 MB read, trivially coalesced.
// ---------------------------------------------------------------------------
__global__ __launch_bounds__(128) void norm_kernel(const float* __restrict__ Amat)
{
    const int p = blockIdx.x * 128 + threadIdx.x;
    float s = 0.f;
    #pragma unroll 8
    for (int r = 0; r < D_DIM; ++r) {
        float v = Amat[(size_t)r * P_DIM + p];
        s += v * v;
    }
    g_inv[p] = 1.f / fmaxf(sqrtf(s), 1e-12f);
}

// ---------------------------------------------------------------------------
// Kernel 1: x = proj @ normalize_cols(A), inner loop on packed fma.rn.f32x2.
// Accumulators packed along m (row pairs) so A-operands load as 8B LDS pairs;
// B scalars are duplicated into f32x2 with one mov each (ALU pipe, overlaps).
// ---------------------------------------------------------------------------
__global__ __launch_bounds__(256) void gemm_norm_kernel(
    const float* __restrict__ proj,   // [M_TOT, D_DIM] row-major
    const float* __restrict__ Amat)   // [D_DIM, P_DIM] row-major
{
    __shared__ __align__(16) float As[BK][BM];   // As[k][m]
    __shared__ __align__(16) float Bs[BK][BN];   // Bs[k][n]

    const int tid = threadIdx.x;
    const int tx  = tid & 15;      // n-direction (4 cols each)
    const int ty  = tid >> 4;      // m-direction (8 rows each)
    const int bx  = blockIdx.x;    // n block
    const int by  = blockIdx.y;    // m block

    u64 acc2[4][4];                // [m-pair][n], each = (m=2q, m=2q+1)
    #pragma unroll
    for (int q = 0; q < 4; ++q)
        #pragma unroll
        for (int j = 0; j < 4; ++j) acc2[q][j] = 0ull;

    const float4* projv = (const float4*)proj;
    const float4* Av    = (const float4*)Amat;

    for (int kt = 0; kt < D_DIM / BK; ++kt) {
        const int k0 = kt * BK;
        // Load proj tile (128 x 16), transpose into As[k][m]
        #pragma unroll
        for (int i = 0; i < 2; ++i) {
            int idx = tid + i * 256;       // 0..511 float4 slots
            int row = idx >> 2;            // 0..127
            int c4  = idx & 3;             // 0..3
            float4 v = projv[(size_t)(by * BM + row) * (D_DIM / 4) + kt * 4 + c4];
            As[c4 * 4 + 0][row] = v.x;
            As[c4 * 4 + 1][row] = v.y;
            As[c4 * 4 + 2][row] = v.z;
            As[c4 * 4 + 3][row] = v.w;
        }
        // Load A tile (16 x 64)
        {
            int r  = tid >> 4;             // 0..15 (k within tile)
            int c4 = tid & 15;             // 0..15 (float4 col)
            float4 v = Av[(size_t)(k0 + r) * (P_DIM / 4) + bx * (BN / 4) + c4];
            *(float4*)&Bs[r][c4 * 4] = v;
        }
        __syncthreads();

        #pragma unroll
        for (int k = 0; k < BK; ++k) {
            // A pairs: consecutive m -> direct 8-byte shared loads
            u64 ap[4];
            #pragma unroll
            for (int q = 0; q < 4; ++q)
                ap[q] = *(const u64*)&As[k][ty * 8 + 2 * q];
            // B scalars, duplicated
            float4 b = *(const float4*)&Bs[k][tx * 4];
            u64 bd[4];
            PACK2(bd[0], b.x, b.x);
            PACK2(bd[1], b.y, b.y);
            PACK2(bd[2], b.z, b.z);
            PACK2(bd[3], b.w, b.w);
            #pragma unroll
            for (int q = 0; q < 4; ++q)
                #pragma unroll
                for (int j = 0; j < 4; ++j)
                    FMA_F32X2(acc2[q][j], ap[q], bd[j], acc2[q][j]);
        }
        __syncthreads();
    }

    const int n0 = bx * BN + tx * 4;
    float inv[4];
    #pragma unroll
    for (int j = 0; j < 4; ++j) inv[j] = g_inv[n0 + j];

    #pragma unroll
    for (int q = 0; q < 4; ++q) {
        float lo[4], hi[4];
        #pragma unroll
        for (int j = 0; j < 4; ++j) UNPACK2(lo[j], hi[j], acc2[q][j]);
        int m = by * BM + ty * 8 + 2 * q;
        float4 o0 = { lo[0] * inv[0], lo[1] * inv[1], lo[2] * inv[2], lo[3] * inv[3] };
        float4 o1 = { hi[0] * inv[0], hi[1] * inv[1], hi[2] * inv[2], hi[3] * inv[3] };
        *(float4*)&g_x[(size_t)m       * P_DIM + n0] = o0;
        *(float4*)&g_x[(size_t)(m + 1) * P_DIM + n0] = o1;
    }
}

// ---------------------------------------------------------------------------
// Kernel 2: per (t,p) accumulate cos/sin means over b with a PACKED Chebyshev
// recurrence: carry a_k=(c_k,s_k) and m_k=(-c_k,-s_k) so each knot step is
//   a_{k+1} = fma(tc, a_k, m_{k-1});  m_{k+1} = fma(-tc, a_k, a_{k-1})
// (2 packed FMA + 1 packed ADD). Two independent b-chains per thread for ILP.
// ---------------------------------------------------------------------------
__global__ __launch_bounds__(64) void trig_kernel()
{
    const int t = blockIdx.y;
    const int p = blockIdx.x * 64 + threadIdx.x;
    const float dt = 3.0f / 16.0f;   // 0.1875

    u64 accp[KNOTS - 1];             // packed (sum_c, sum_s), k = 1..16
    #pragma unroll
    for (int k = 0; k < KNOTS - 1; ++k) accp[k] = 0ull;

    const float* xp = g_x + (size_t)(t * B_DIM) * P_DIM + p;
    for (int b = 0; b < B_DIM; b += 2) {
        float x0 = xp[(size_t)b * P_DIM];
        float x1 = xp[(size_t)(b + 1) * P_DIM];
        float s0, c0, s1, c1;
        __sincosf(x0 * dt, &s0, &c0);
        __sincosf(x1 * dt, &s1, &c1);

        u64 a0, m0, ap0, mp0, tc0, ntc0;
        u64 a1, m1, ap1, mp1, tc1, ntc1;
        PACK2(a0, c0, s0);   PACK2(m0, -c0, -s0);
        PACK2(ap0, 1.f, 0.f); PACK2(mp0, -1.f, 0.f);
        PACK2(tc0, 2.f * c0, 2.f * c0); PACK2(ntc0, -2.f * c0, -2.f * c0);
        PACK2(a1, c1, s1);   PACK2(m1, -c1, -s1);
        PACK2(ap1, 1.f, 0.f); PACK2(mp1, -1.f, 0.f);
        PACK2(tc1, 2.f * c1, 2.f * c1); PACK2(ntc1, -2.f * c1, -2.f * c1);

        #pragma unroll
        for (int k = 1; k <= 16; ++k) {
            u64 s;
            ADD_F32X2_(s, a0, a1);
            ADD_F32X2_(accp[k - 1], accp[k - 1], s);
            u64 an0, mn0, an1, mn1;
            FMA_F32X2(an0, tc0,  a0, mp0);
            FMA_F32X2(mn0, ntc0, a0, ap0);
            FMA_F32X2(an1, tc1,  a1, mp1);
            FMA_F32X2(mn1, ntc1, a1, ap1);
            ap0 = a0; mp0 = m0; a0 = an0; m0 = mn0;
            ap1 = a1; mp1 = m1; a1 = an1; m1 = mn1;
        }
    }

    float val = 0.f;
    const float invB = 1.f / (float)B_DIM;
    #pragma unroll
    for (int k = 1; k <= 16; ++k) {
        float tk   = (float)k * dt;
        float phik = expf(-0.5f * tk * tk);
        float wk   = ((k == 16) ? dt : 2.f * dt) * phik;
        float cs, ss;
        UNPACK2(cs, ss, accp[k - 1]);
        float cm = cs * invB - phik;
        float sm = ss * invB;
        val += wk * (cm * cm + sm * sm);
    }
    val *= (float)B_DIM;   // * B

    __shared__ float red[64];
    red[threadIdx.x] = val;
    __syncthreads();
    #pragma unroll
    for (int s = 32; s > 0; s >>= 1) {
        if (threadIdx.x < s) red[threadIdx.x] += red[threadIdx.x + s];
        __syncthreads();
    }
    if (threadIdx.x == 0)
        g_partial[blockIdx.y * gridDim.x + blockIdx.x] = red[0];
}

// ---------------------------------------------------------------------------
// Kernel 3: final deterministic reduction of 512 partials, divide by T*P.
// ---------------------------------------------------------------------------
__global__ __launch_bounds__(512) void reduce_kernel(float* __restrict__ out)
{
    __shared__ float red[512];
    red[threadIdx.x] = g_partial[threadIdx.x];
    __syncthreads();
    #pragma unroll
    for (int s = 256; s > 0; s >>= 1) {
        if (threadIdx.x < s) red[threadIdx.x] += red[threadIdx.x + s];
        __syncthreads();
    }
    if (threadIdx.x == 0)
        out[0] = red[0] * (1.0f / (float)(T_DIM * P_DIM));
}

// ---------------------------------------------------------------------------
extern "C" void kernel_launch(void* const* d_in, const int* in_sizes, int n_in,
                              void* d_out, int out_size)
{
    const float* proj = (const float*)d_in[0];   // (32,64,256)
    const float* Amat = (const float*)d_in[1];   // (256,1024)
    float* out = (float*)d_out;

    norm_kernel<<<P_DIM / 128, 128>>>(Amat);

    dim3 g1(P_DIM / BN, M_TOT / BM);   // (16, 16)
    gemm_norm_kernel<<<g1, 256>>>(proj, Amat);

    dim3 g2(P_DIM / 64, T_DIM);        // (16, 32) -> 512 blocks
    trig_kernel<<<g2, 64>>>();

    reduce_kernel<<<1, 512>>>(out);
}

// round 4
// speedup vs baseline: 1.5712x; 1.5712x over previous
#include <cuda_runtime.h>
#include <cstdint>

// Problem dims
#define T_DIM 32
#define B_DIM 64
#define D_DIM 256
#define P_DIM 1024
#define M_TOT (T_DIM * B_DIM)   // 2048
#define KNOTS 17

// Scratch (static device globals — no runtime allocation)
__device__ float g_x[M_TOT * P_DIM];     // 8 MB: projections x[t*B+b][p]
__device__ float g_pt[M_TOT * D_DIM];    // 2 MB: proj pre-rounded to tf32
__device__ float g_Bt[P_DIM * D_DIM];    // 1 MB: normalized A^T, tf32-rounded
__device__ float g_partial[256];
__device__ int   g_count = 0;

__device__ __forceinline__ float f2tf32(float f)
{
    uint32_t u;
    asm("cvt.rna.tf32.f32 %0, %1;" : "=r"(u) : "f"(f));
    return __uint_as_float(u);
}

// ---------------------------------------------------------------------------
// Kernel 0 (fused prep), grid.x = 64:
//  bx <  32 : column norms of A + transpose + scale + tf32-round -> g_Bt
//  bx >= 32 : tf32-round proj -> g_pt
// ---------------------------------------------------------------------------
__global__ __launch_bounds__(256) void prep_kernel(
    const float* __restrict__ proj, const float* __restrict__ Amat)
{
    if (blockIdx.x >= 32) {
        // proj convert: slab of 4096 float4
        const int slab = blockIdx.x - 32;
        const float4* src = (const float4*)proj;
        float4* dst = (float4*)g_pt;
        #pragma unroll
        for (int i = 0; i < 16; ++i) {
            int idx = slab * 4096 + i * 256 + threadIdx.x;
            float4 v = src[idx];
            v.x = f2tf32(v.x); v.y = f2tf32(v.y);
            v.z = f2tf32(v.z); v.w = f2tf32(v.w);
            dst[idx] = v;
        }
        return;
    }

    __shared__ float tile[D_DIM][33];
    __shared__ float ps[8][32];
    __shared__ float invs[32];

    const int tid  = threadIdx.x;
    const int lane = tid & 31;
    const int wr   = tid >> 5;
    const int p0   = blockIdx.x * 32;

    #pragma unroll
    for (int j = 0; j < 32; ++j) {
        int d = wr * 32 + j;
        tile[d][lane] = Amat[(size_t)d * P_DIM + p0 + lane];
    }
    __syncthreads();

    float s = 0.f;
    #pragma unroll
    for (int j = 0; j < 32; ++j) {
        float v = tile[wr * 32 + j][lane];
        s += v * v;
    }
    ps[wr][lane] = s;
    __syncthreads();
    if (wr == 0) {
        float t = 0.f;
        #pragma unroll
        for (int w = 0; w < 8; ++w) t += ps[w][lane];
        invs[lane] = 1.f / fmaxf(sqrtf(t), 1e-12f);
    }
    __syncthreads();

    const int pl = tid >> 3;          // 0..31
    const int dc = (tid & 7) * 32;    // 0..224
    const float inv = invs[pl];
    #pragma unroll
    for (int j = 0; j < 32; ++j)
        g_Bt[(size_t)(p0 + pl) * D_DIM + dc + j] = f2tf32(tile[dc + j][pl] * inv);
}

// ---------------------------------------------------------------------------
// Kernel 1: tf32 mma.sync GEMM.  C[2048,1024] = g_pt @ g_Bt^T.
// CTA 128x128, K chunks of 64, double-buffered cp.async; 8 warps 64x32 tiles.
// ---------------------------------------------------------------------------
#define ROWSTRIDE 68                        // floats per smem row (pad)
#define CHUNK_F   (128 * ROWSTRIDE)         // 8704 floats per buffer
#define GEMM_SMEM (4 * CHUNK_F * 4)         // 2 ops x 2 bufs = 139264 B

__device__ __forceinline__ void load_chunk(
    uint32_t sb, int buf, int kt, int m0, int n0,
    const float4* __restrict__ pa, const float4* __restrict__ pb, int tid)
{
    #pragma unroll
    for (int t = 0; t < 8; ++t) {
        int idx = t * 256 + tid;            // 0..2047
        int row = idx >> 4;                 // 0..127
        int c   = idx & 15;                 // 0..15 float4 within 64-float row
        uint32_t off = (uint32_t)((buf * CHUNK_F + row * ROWSTRIDE + c * 4) * 4);
        const float4* sa = pa + (size_t)(m0 + row) * (D_DIM / 4) + kt * 16 + c;
        const float4* sbp = pb + (size_t)(n0 + row) * (D_DIM / 4) + kt * 16 + c;
        asm volatile("cp.async.cg.shared.global [%0], [%1], 16;"
                     :: "r"(sb + off), "l"(sa));
        asm volatile("cp.async.cg.shared.global [%0], [%1], 16;"
                     :: "r"(sb + (uint32_t)(2 * CHUNK_F * 4) + off), "l"(sbp));
    }
}

__global__ __launch_bounds__(256, 1) void gemm_tc(
    const float* __restrict__ pA, const float* __restrict__ pB)
{
    extern __shared__ float sm[];
    uint32_t sb;
    asm("{ .reg .u64 t; cvta.to.shared.u64 t, %1; cvt.u32.u64 %0, t; }"
        : "=r"(sb) : "l"(sm));

    const int tid = threadIdx.x;
    const int wid = tid >> 5;
    const int lid = tid & 31;
    const int gid = lid >> 2;      // 0..7
    const int tig = lid & 3;       // 0..3
    const int wm  = (wid >> 2) * 64;
    const int wn  = (wid & 3) * 32;
    const int m0  = blockIdx.y * 128;
    const int n0  = blockIdx.x * 128;

    const float4* pa = (const float4*)pA;
    const float4* pb = (const float4*)pB;

    float acc[4][4][4];
    #pragma unroll
    for (int mi = 0; mi < 4; ++mi)
        #pragma unroll
        for (int ni = 0; ni < 4; ++ni)
            #pragma unroll
            for (int r = 0; r < 4; ++r) acc[mi][ni][r] = 0.f;

    load_chunk(sb, 0, 0, m0, n0, pa, pb, tid);
    asm volatile("cp.async.commit_group;" ::: "memory");

    #pragma unroll
    for (int kt = 0; kt < 4; ++kt) {
        if (kt < 3) {
            load_chunk(sb, (kt + 1) & 1, kt + 1, m0, n0, pa, pb, tid);
            asm volatile("cp.async.commit_group;" ::: "memory");
            asm volatile("cp.async.wait_group 1;" ::: "memory");
        } else {
            asm volatile("cp.async.wait_group 0;" ::: "memory");
        }
        __syncthreads();

        const int buf = kt & 1;
        const float* As = sm + buf * CHUNK_F;
        const float* Bs = sm + 2 * CHUNK_F + buf * CHUNK_F;

        #pragma unroll
        for (int ks = 0; ks < 8; ++ks) {
            const int kc = ks * 8;
            uint32_t a[4][4];
            #pragma unroll
            for (int mi = 0; mi < 4; ++mi) {
                const float* ap = As + (wm + mi * 16 + gid) * ROWSTRIDE + kc + tig;
                a[mi][0] = __float_as_uint(ap[0]);
                a[mi][1] = __float_as_uint(ap[8 * ROWSTRIDE]);
                a[mi][2] = __float_as_uint(ap[4]);
                a[mi][3] = __float_as_uint(ap[8 * ROWSTRIDE + 4]);
            }
            uint32_t b[4][2];
            #pragma unroll
            for (int ni = 0; ni < 4; ++ni) {
                const float* bp = Bs + (wn + ni * 8 + gid) * ROWSTRIDE + kc + tig;
                b[ni][0] = __float_as_uint(bp[0]);
                b[ni][1] = __float_as_uint(bp[4]);
            }
            #pragma unroll
            for (int mi = 0; mi < 4; ++mi)
                #pragma unroll
                for (int ni = 0; ni < 4; ++ni)
                    asm volatile(
                        "mma.sync.aligned.m16n8k8.row.col.f32.tf32.tf32.f32 "
                        "{%0,%1,%2,%3}, {%4,%5,%6,%7}, {%8,%9}, {%0,%1,%2,%3};"
                        : "+f"(acc[mi][ni][0]), "+f"(acc[mi][ni][1]),
                          "+f"(acc[mi][ni][2]), "+f"(acc[mi][ni][3])
                        : "r"(a[mi][0]), "r"(a[mi][1]), "r"(a[mi][2]), "r"(a[mi][3]),
                          "r"(b[ni][0]), "r"(b[ni][1]));
        }
        __syncthreads();
    }

    // Epilogue: C fragment mapping -> g_x
    #pragma unroll
    for (int mi = 0; mi < 4; ++mi) {
        const int m = m0 + wm + mi * 16 + gid;
        #pragma unroll
        for (int ni = 0; ni < 4; ++ni) {
            const int n = n0 + wn + ni * 8 + tig * 2;
            float2 v0 = { acc[mi][ni][0], acc[mi][ni][1] };
            float2 v1 = { acc[mi][ni][2], acc[mi][ni][3] };
            *(float2*)&g_x[(size_t)m * P_DIM + n]       = v0;
            *(float2*)&g_x[(size_t)(m + 8) * P_DIM + n] = v1;
        }
    }
}

// ---------------------------------------------------------------------------
// Kernel 2: per (t,p) cos/sin means over b via Chebyshev recurrence,
// weighted error, block partials, and fused last-block final reduction.
// ---------------------------------------------------------------------------
__global__ __launch_bounds__(128) void trig_kernel(float* __restrict__ out)
{
    const int t = blockIdx.y;
    const int p = blockIdx.x * 128 + threadIdx.x;
    const float dt = 3.0f / 16.0f;

    float ca[KNOTS - 1];
    float sa[KNOTS - 1];
    #pragma unroll
    for (int k = 0; k < KNOTS - 1; ++k) { ca[k] = 0.f; sa[k] = 0.f; }

    const float* xp = g_x + (size_t)(t * B_DIM) * P_DIM + p;
    #pragma unroll 4
    for (int b = 0; b < B_DIM; ++b) {
        float x = xp[(size_t)b * P_DIM];
        float s1, c1;
        __sincosf(x * dt, &s1, &c1);
        float ckm = 1.f, skm = 0.f;
        float ck = c1, sk = s1;
        const float tc = 2.f * c1;
        #pragma unroll
        for (int k = 1; k <= 16; ++k) {
            ca[k - 1] += ck;
            sa[k - 1] += sk;
            float cn = tc * ck - ckm;
            float sn = tc * sk - skm;
            ckm = ck; skm = sk; ck = cn; sk = sn;
        }
    }

    float val = 0.f;
    const float invB = 1.f / (float)B_DIM;
    #pragma unroll
    for (int k = 1; k <= 16; ++k) {
        float tk   = (float)k * dt;
        float phik = expf(-0.5f * tk * tk);
        float wk   = ((k == 16) ? dt : 2.f * dt) * phik;
        float cm = ca[k - 1] * invB - phik;
        float sm = sa[k - 1] * invB;
        val += wk * (cm * cm + sm * sm);
    }
    val *= (float)B_DIM;

    __shared__ float red[128];
    red[threadIdx.x] = val;
    __syncthreads();
    #pragma unroll
    for (int s = 64; s > 0; s >>= 1) {
        if (threadIdx.x < s) red[threadIdx.x] += red[threadIdx.x + s];
        __syncthreads();
    }

    __shared__ int is_last;
    if (threadIdx.x == 0) {
        g_partial[blockIdx.y * gridDim.x + blockIdx.x] = red[0];
        __threadfence();
        int prev = atomicAdd(&g_count, 1);
        is_last = (prev == (int)(gridDim.x * gridDim.y) - 1);
    }
    __syncthreads();

    if (is_last) {
        float v = g_partial[threadIdx.x] + g_partial[threadIdx.x + 128];
        red[threadIdx.x] = v;
        __syncthreads();
        #pragma unroll
        for (int s = 64; s > 0; s >>= 1) {
            if (threadIdx.x < s) red[threadIdx.x] += red[threadIdx.x + s];
            __syncthreads();
        }
        if (threadIdx.x == 0) {
            out[0] = red[0] * (1.0f / (float)(T_DIM * P_DIM));
            g_count = 0;   // reset for next (deterministic) invocation
        }
    }
}

// ---------------------------------------------------------------------------
extern "C" void kernel_launch(void* const* d_in, const int* in_sizes, int n_in,
                              void* d_out, int out_size)
{
    const float* proj = (const float*)d_in[0];   // (32,64,256)
    const float* Amat = (const float*)d_in[1];   // (256,1024)
    float* out = (float*)d_out;

    cudaFuncSetAttribute(gemm_tc, cudaFuncAttributeMaxDynamicSharedMemorySize,
                         GEMM_SMEM);

    prep_kernel<<<64, 256>>>(proj, Amat);

    float *pt, *bt;
    cudaGetSymbolAddress((void**)&pt, g_pt);
    cudaGetSymbolAddress((void**)&bt, g_Bt);
    dim3 g1(P_DIM / 128, M_TOT / 128);   // (8, 16)
    gemm_tc<<<g1, 256, GEMM_SMEM>>>(pt, bt);

    dim3 g2(P_DIM / 128, T_DIM);         // (8, 32) -> 256 blocks
    trig_kernel<<<g2, 128>>>(out);
}

// round 5
// speedup vs baseline: 1.6769x; 1.0673x over previous
#include <cuda_runtime.h>
#include <cstdint>

// Problem dims
#define T_DIM 32
#define B_DIM 64
#define D_DIM 256
#define P_DIM 1024
#define M_TOT (T_DIM * B_DIM)   // 2048
#define KNOTS 17

// Scratch (static device globals — no runtime allocation)
__device__ float g_x[M_TOT * P_DIM];     // 8 MB: raw proj@A (tf32 product)
__device__ float g_pt[M_TOT * D_DIM];    // 2 MB: proj pre-rounded to tf32
__device__ float g_inv[P_DIM];           // 1/||A_col||
__device__ float g_partial[256];
__device__ int   g_count = 0;

__device__ __forceinline__ float f2tf32(float f)
{
    uint32_t u;
    asm("cvt.rna.tf32.f32 %0, %1;" : "=r"(u) : "f"(f));
    return __uint_as_float(u);
}

// ---------------------------------------------------------------------------
// Kernel 0 (fused prep), 68 blocks x 256:
//  bx < 64 : tf32-round proj -> g_pt    (2 MB RW, coalesced float4)
//  bx >= 64: column inverse norms of A  (4 blocks x 256 = 1024 = P threads)
// ---------------------------------------------------------------------------
__global__ __launch_bounds__(256) void prep_kernel(
    const float* __restrict__ proj, const float* __restrict__ Amat)
{
    if (blockIdx.x < 64) {
        const float4* src = (const float4*)proj;
        float4* dst = (float4*)g_pt;
        #pragma unroll
        for (int i = 0; i < 8; ++i) {
            int idx = blockIdx.x * 2048 + i * 256 + threadIdx.x;
            float4 v = src[idx];
            v.x = f2tf32(v.x); v.y = f2tf32(v.y);
            v.z = f2tf32(v.z); v.w = f2tf32(v.w);
            dst[idx] = v;
        }
    } else {
        const int p = (blockIdx.x - 64) * 256 + threadIdx.x;
        float s = 0.f;
        #pragma unroll 8
        for (int d = 0; d < D_DIM; ++d) {
            float v = Amat[(size_t)d * P_DIM + p];
            s += v * v;
        }
        g_inv[p] = 1.f / fmaxf(sqrtf(s), 1e-12f);
    }
}

// ---------------------------------------------------------------------------
// Kernel 1: tf32 mma.sync GEMM.  C[2048,1024] = g_pt @ A  (raw, unnormalized).
// A-operand smem [m=128][k=64] stride 68; B-operand smem holds the A matrix
// tile in NATIVE [k=64][n=128] layout, stride 136 (bank-perfect), cp.async'd
// straight from Amat — no transpose pass.  B cvt.rna at fragment load.
// ---------------------------------------------------------------------------
#define ASTRIDE 68
#define BSTRIDE 136
#define CHUNKA_F (128 * ASTRIDE)            // 8704 floats
#define CHUNKB_F (64 * BSTRIDE)             // 8704 floats
#define GEMM_SMEM ((2 * CHUNKA_F + 2 * CHUNKB_F) * 4)   // 139264 B

__device__ __forceinline__ void load_chunk(
    uint32_t sb, int buf, int kt, int m0, int n0,
    const float4* __restrict__ pa, const float4* __restrict__ pb, int tid)
{
    // A tile: 128 rows (m) x 16 float4 (k)
    #pragma unroll
    for (int t = 0; t < 8; ++t) {
        int idx = t * 256 + tid;
        int row = idx >> 4;                 // 0..127
        int c   = idx & 15;                 // 0..15
        uint32_t off = (uint32_t)((buf * CHUNKA_F + row * ASTRIDE + c * 4) * 4);
        const float4* s = pa + (size_t)(m0 + row) * (D_DIM / 4) + kt * 16 + c;
        asm volatile("cp.async.cg.shared.global [%0], [%1], 16;"
                     :: "r"(sb + off), "l"(s));
    }
    // B tile: 64 rows (k=d) x 32 float4 (n=p), native Amat layout
    #pragma unroll
    for (int t = 0; t < 8; ++t) {
        int idx = t * 256 + tid;
        int row = idx >> 5;                 // 0..63
        int c   = idx & 31;                 // 0..31
        uint32_t off = (uint32_t)((2 * CHUNKA_F + buf * CHUNKB_F
                                   + row * BSTRIDE + c * 4) * 4);
        const float4* s = pb + (size_t)(kt * 64 + row) * (P_DIM / 4) + n0 / 4 + c;
        asm volatile("cp.async.cg.shared.global [%0], [%1], 16;"
                     :: "r"(sb + off), "l"(s));
    }
}

__global__ __launch_bounds__(256, 1) void gemm_tc(
    const float* __restrict__ pA, const float* __restrict__ pB)
{
    extern __shared__ float sm[];
    uint32_t sb;
    asm("{ .reg .u64 t; cvta.to.shared.u64 t, %1; cvt.u32.u64 %0, t; }"
        : "=r"(sb) : "l"(sm));

    const int tid = threadIdx.x;
    const int wid = tid >> 5;
    const int lid = tid & 31;
    const int gid = lid >> 2;      // 0..7
    const int tig = lid & 3;       // 0..3
    const int wm  = (wid >> 2) * 64;
    const int wn  = (wid & 3) * 32;
    const int m0  = blockIdx.y * 128;
    const int n0  = blockIdx.x * 128;

    const float4* pa = (const float4*)pA;
    const float4* pb = (const float4*)pB;

    float acc[4][4][4];
    #pragma unroll
    for (int mi = 0; mi < 4; ++mi)
        #pragma unroll
        for (int ni = 0; ni < 4; ++ni)
            #pragma unroll
            for (int r = 0; r < 4; ++r) acc[mi][ni][r] = 0.f;

    load_chunk(sb, 0, 0, m0, n0, pa, pb, tid);
    asm volatile("cp.async.commit_group;" ::: "memory");

    #pragma unroll
    for (int kt = 0; kt < 4; ++kt) {
        if (kt < 3) {
            load_chunk(sb, (kt + 1) & 1, kt + 1, m0, n0, pa, pb, tid);
            asm volatile("cp.async.commit_group;" ::: "memory");
            asm volatile("cp.async.wait_group 1;" ::: "memory");
        } else {
            asm volatile("cp.async.wait_group 0;" ::: "memory");
        }
        __syncthreads();

        const int buf = kt & 1;
        const float* As = sm + buf * CHUNKA_F;
        const float* Bs = sm + 2 * CHUNKA_F + buf * CHUNKB_F;

        #pragma unroll
        for (int ks = 0; ks < 8; ++ks) {
            const int kc = ks * 8;
            uint32_t a[4][4];
            #pragma unroll
            for (int mi = 0; mi < 4; ++mi) {
                const float* ap = As + (wm + mi * 16 + gid) * ASTRIDE + kc + tig;
                a[mi][0] = __float_as_uint(ap[0]);
                a[mi][1] = __float_as_uint(ap[8 * ASTRIDE]);
                a[mi][2] = __float_as_uint(ap[4]);
                a[mi][3] = __float_as_uint(ap[8 * ASTRIDE + 4]);
            }
            uint32_t b[4][2];
            #pragma unroll
            for (int ni = 0; ni < 4; ++ni) {
                const float* bp = Bs + (kc + tig) * BSTRIDE + wn + ni * 8 + gid;
                b[ni][0] = __float_as_uint(f2tf32(bp[0]));
                b[ni][1] = __float_as_uint(f2tf32(bp[4 * BSTRIDE]));
            }
            #pragma unroll
            for (int mi = 0; mi < 4; ++mi)
                #pragma unroll
                for (int ni = 0; ni < 4; ++ni)
                    asm volatile(
                        "mma.sync.aligned.m16n8k8.row.col.f32.tf32.tf32.f32 "
                        "{%0,%1,%2,%3}, {%4,%5,%6,%7}, {%8,%9}, {%0,%1,%2,%3};"
                        : "+f"(acc[mi][ni][0]), "+f"(acc[mi][ni][1]),
                          "+f"(acc[mi][ni][2]), "+f"(acc[mi][ni][3])
                        : "r"(a[mi][0]), "r"(a[mi][1]), "r"(a[mi][2]), "r"(a[mi][3]),
                          "r"(b[ni][0]), "r"(b[ni][1]));
        }
        __syncthreads();
    }

    #pragma unroll
    for (int mi = 0; mi < 4; ++mi) {
        const int m = m0 + wm + mi * 16 + gid;
        #pragma unroll
        for (int ni = 0; ni < 4; ++ni) {
            const int n = n0 + wn + ni * 8 + tig * 2;
            float2 v0 = { acc[mi][ni][0], acc[mi][ni][1] };
            float2 v1 = { acc[mi][ni][2], acc[mi][ni][3] };
            *(float2*)&g_x[(size_t)m * P_DIM + n]       = v0;
            *(float2*)&g_x[(size_t)(m + 8) * P_DIM + n] = v1;
        }
    }
}

// ---------------------------------------------------------------------------
// Kernel 2: per (t,p) cos/sin means over b via Chebyshev recurrence.
// Column normalization folded into the angle scale: angle = x * (dt*inv[p]).
// Fused deterministic final reduction via last-block counter.
// ---------------------------------------------------------------------------
__global__ __launch_bounds__(128) void trig_kernel(float* __restrict__ out)
{
    const int t = blockIdx.y;
    const int p = blockIdx.x * 128 + threadIdx.x;
    const float dt = 3.0f / 16.0f;
    const float sc = dt * g_inv[p];

    float ca[KNOTS - 1];
    float sa[KNOTS - 1];
    #pragma unroll
    for (int k = 0; k < KNOTS - 1; ++k) { ca[k] = 0.f; sa[k] = 0.f; }

    const float* xp = g_x + (size_t)(t * B_DIM) * P_DIM + p;
    #pragma unroll 4
    for (int b = 0; b < B_DIM; ++b) {
        float x = xp[(size_t)b * P_DIM];
        float s1, c1;
        __sincosf(x * sc, &s1, &c1);
        float ckm = 1.f, skm = 0.f;
        float ck = c1, sk = s1;
        const float tc = 2.f * c1;
        #pragma unroll
        for (int k = 1; k <= 16; ++k) {
            ca[k - 1] += ck;
            sa[k - 1] += sk;
            float cn = tc * ck - ckm;
            float sn = tc * sk - skm;
            ckm = ck; skm = sk; ck = cn; sk = sn;
        }
    }

    float val = 0.f;
    const float invB = 1.f / (float)B_DIM;
    #pragma unroll
    for (int k = 1; k <= 16; ++k) {
        float tk   = (float)k * dt;
        float phik = expf(-0.5f * tk * tk);
        float wk   = ((k == 16) ? dt : 2.f * dt) * phik;
        float cm = ca[k - 1] * invB - phik;
        float sm = sa[k - 1] * invB;
        val += wk * (cm * cm + sm * sm);
    }
    val *= (float)B_DIM;

    __shared__ float red[128];
    red[threadIdx.x] = val;
    __syncthreads();
    #pragma unroll
    for (int s = 64; s > 0; s >>= 1) {
        if (threadIdx.x < s) red[threadIdx.x] += red[threadIdx.x + s];
        __syncthreads();
    }

    __shared__ int is_last;
    if (threadIdx.x == 0) {
        g_partial[blockIdx.y * gridDim.x + blockIdx.x] = red[0];
        __threadfence();
        int prev = atomicAdd(&g_count, 1);
        is_last = (prev == (int)(gridDim.x * gridDim.y) - 1);
    }
    __syncthreads();

    if (is_last) {
        float v = g_partial[threadIdx.x] + g_partial[threadIdx.x + 128];
        red[threadIdx.x] = v;
        __syncthreads();
        #pragma unroll
        for (int s = 64; s > 0; s >>= 1) {
            if (threadIdx.x < s) red[threadIdx.x] += red[threadIdx.x + s];
            __syncthreads();
        }
        if (threadIdx.x == 0) {
            out[0] = red[0] * (1.0f / (float)(T_DIM * P_DIM));
            g_count = 0;   // reset so graph replays are deterministic
        }
    }
}

// ---------------------------------------------------------------------------
extern "C" void kernel_launch(void* const* d_in, const int* in_sizes, int n_in,
                              void* d_out, int out_size)
{
    const float* proj = (const float*)d_in[0];   // (32,64,256)
    const float* Amat = (const float*)d_in[1];   // (256,1024)
    float* out = (float*)d_out;

    cudaFuncSetAttribute(gemm_tc, cudaFuncAttributeMaxDynamicSharedMemorySize,
                         GEMM_SMEM);

    prep_kernel<<<68, 256>>>(proj, Amat);

    float* pt;
    cudaGetSymbolAddress((void**)&pt, g_pt);
    dim3 g1(P_DIM / 128, M_TOT / 128);   // (8, 16)
    gemm_tc<<<g1, 256, GEMM_SMEM>>>(pt, Amat);

    dim3 g2(P_DIM / 128, T_DIM);         // (8, 32) -> 256 blocks
    trig_kernel<<<g2, 128>>>(out);
}

// round 6
// speedup vs baseline: 1.8957x; 1.1304x over previous
#include <cuda_runtime.h>
#include <cstdint>

// Problem dims
#define T_DIM 32
#define B_DIM 64
#define D_DIM 256
#define P_DIM 1024
#define M_TOT (T_DIM * B_DIM)   // 2048
#define KNOTS 17

// Scratch (static device globals — no runtime allocation)
__device__ float g_x[M_TOT * P_DIM];     // 8 MB: raw proj@A (tf32 product)
__device__ float g_inv[P_DIM];           // 1/||A_col||
__device__ float g_partial[256];
__device__ int   g_count = 0;

__device__ __forceinline__ float f2tf32(float f)
{
    uint32_t u;
    asm("cvt.rna.tf32.f32 %0, %1;" : "=r"(u) : "f"(f));
    return __uint_as_float(u);
}

// ---------------------------------------------------------------------------
// Kernel 0: column inverse norms of A. 32 blocks x 256 threads.
// Block b owns 32 p-columns; thread (tx,ty) = (p, d-slice) sums 32 elements
// (coalesced, MLP-unrolled), then 8-way SMEM combine. ~4 latency waves.
// ---------------------------------------------------------------------------
__global__ __launch_bounds__(256) void norm_kernel(const float* __restrict__ Amat)
{
    __shared__ float ps[8][32];
    const int tx = threadIdx.x & 31;   // p within block
    const int ty = threadIdx.x >> 5;   // d slice 0..7
    const int p  = blockIdx.x * 32 + tx;

    float s = 0.f;
    #pragma unroll
    for (int j = 0; j < 32; ++j) {
        float v = Amat[(size_t)(ty + j * 8) * P_DIM + p];
        s += v * v;
    }
    ps[ty][tx] = s;
    __syncthreads();
    if (ty == 0) {
        float t = 0.f;
        #pragma unroll
        for (int w = 0; w < 8; ++w) t += ps[w][tx];
        g_inv[p] = 1.f / fmaxf(sqrtf(t), 1e-12f);
    }
}

// ---------------------------------------------------------------------------
// Kernel 1: tf32 mma.sync GEMM.  C[2048,1024] = proj @ A  (raw, unnormalized).
// Both operands cp.async'd RAW from global (no prep pass); cvt.rna.tf32
// applied in-register at fragment load.  A smem [m=128][k=64] stride 68;
// B smem holds A-matrix tile in NATIVE [k=64][n=128] layout, stride 136.
// ---------------------------------------------------------------------------
#define ASTRIDE 68
#define BSTRIDE 136
#define CHUNKA_F (128 * ASTRIDE)            // 8704 floats
#define CHUNKB_F (64 * BSTRIDE)             // 8704 floats
#define GEMM_SMEM ((2 * CHUNKA_F + 2 * CHUNKB_F) * 4)   // 139264 B

__device__ __forceinline__ void load_chunk(
    uint32_t sb, int buf, int kt, int m0, int n0,
    const float4* __restrict__ pa, const float4* __restrict__ pb, int tid)
{
    // A tile: 128 rows (m) x 16 float4 (k)
    #pragma unroll
    for (int t = 0; t < 8; ++t) {
        int idx = t * 256 + tid;
        int row = idx >> 4;                 // 0..127
        int c   = idx & 15;                 // 0..15
        uint32_t off = (uint32_t)((buf * CHUNKA_F + row * ASTRIDE + c * 4) * 4);
        const float4* s = pa + (size_t)(m0 + row) * (D_DIM / 4) + kt * 16 + c;
        asm volatile("cp.async.cg.shared.global [%0], [%1], 16;"
                     :: "r"(sb + off), "l"(s));
    }
    // B tile: 64 rows (k=d) x 32 float4 (n=p), native Amat layout
    #pragma unroll
    for (int t = 0; t < 8; ++t) {
        int idx = t * 256 + tid;
        int row = idx >> 5;                 // 0..63
        int c   = idx & 31;                 // 0..31
        uint32_t off = (uint32_t)((2 * CHUNKA_F + buf * CHUNKB_F
                                   + row * BSTRIDE + c * 4) * 4);
        const float4* s = pb + (size_t)(kt * 64 + row) * (P_DIM / 4) + n0 / 4 + c;
        asm volatile("cp.async.cg.shared.global [%0], [%1], 16;"
                     :: "r"(sb + off), "l"(s));
    }
}

__global__ __launch_bounds__(256, 1) void gemm_tc(
    const float* __restrict__ pA, const float* __restrict__ pB)
{
    extern __shared__ float sm[];
    uint32_t sb;
    asm("{ .reg .u64 t; cvta.to.shared.u64 t, %1; cvt.u32.u64 %0, t; }"
        : "=r"(sb) : "l"(sm));

    const int tid = threadIdx.x;
    const int wid = tid >> 5;
    const int lid = tid & 31;
    const int gid = lid >> 2;      // 0..7
    const int tig = lid & 3;       // 0..3
    const int wm  = (wid >> 2) * 64;
    const int wn  = (wid & 3) * 32;
    const int m0  = blockIdx.y * 128;
    const int n0  = blockIdx.x * 128;

    const float4* pa = (const float4*)pA;
    const float4* pb = (const float4*)pB;

    float acc[4][4][4];
    #pragma unroll
    for (int mi = 0; mi < 4; ++mi)
        #pragma unroll
        for (int ni = 0; ni < 4; ++ni)
            #pragma unroll
            for (int r = 0; r < 4; ++r) acc[mi][ni][r] = 0.f;

    load_chunk(sb, 0, 0, m0, n0, pa, pb, tid);
    asm volatile("cp.async.commit_group;" ::: "memory");

    #pragma unroll
    for (int kt = 0; kt < 4; ++kt) {
        if (kt < 3) {
            load_chunk(sb, (kt + 1) & 1, kt + 1, m0, n0, pa, pb, tid);
            asm volatile("cp.async.commit_group;" ::: "memory");
            asm volatile("cp.async.wait_group 1;" ::: "memory");
        } else {
            asm volatile("cp.async.wait_group 0;" ::: "memory");
        }
        __syncthreads();

        const int buf = kt & 1;
        const float* As = sm + buf * CHUNKA_F;
        const float* Bs = sm + 2 * CHUNKA_F + buf * CHUNKB_F;

        #pragma unroll
        for (int ks = 0; ks < 8; ++ks) {
            const int kc = ks * 8;
            uint32_t a[4][4];
            #pragma unroll
            for (int mi = 0; mi < 4; ++mi) {
                const float* ap = As + (wm + mi * 16 + gid) * ASTRIDE + kc + tig;
                a[mi][0] = __float_as_uint(f2tf32(ap[0]));
                a[mi][1] = __float_as_uint(f2tf32(ap[8 * ASTRIDE]));
                a[mi][2] = __float_as_uint(f2tf32(ap[4]));
                a[mi][3] = __float_as_uint(f2tf32(ap[8 * ASTRIDE + 4]));
            }
            uint32_t b[4][2];
            #pragma unroll
            for (int ni = 0; ni < 4; ++ni) {
                const float* bp = Bs + (kc + tig) * BSTRIDE + wn + ni * 8 + gid;
                b[ni][0] = __float_as_uint(f2tf32(bp[0]));
                b[ni][1] = __float_as_uint(f2tf32(bp[4 * BSTRIDE]));
            }
            #pragma unroll
            for (int mi = 0; mi < 4; ++mi)
                #pragma unroll
                for (int ni = 0; ni < 4; ++ni)
                    asm volatile(
                        "mma.sync.aligned.m16n8k8.row.col.f32.tf32.tf32.f32 "
                        "{%0,%1,%2,%3}, {%4,%5,%6,%7}, {%8,%9}, {%0,%1,%2,%3};"
                        : "+f"(acc[mi][ni][0]), "+f"(acc[mi][ni][1]),
                          "+f"(acc[mi][ni][2]), "+f"(acc[mi][ni][3])
                        : "r"(a[mi][0]), "r"(a[mi][1]), "r"(a[mi][2]), "r"(a[mi][3]),
                          "r"(b[ni][0]), "r"(b[ni][1]));
        }
        __syncthreads();
    }

    #pragma unroll
    for (int mi = 0; mi < 4; ++mi) {
        const int m = m0 + wm + mi * 16 + gid;
        #pragma unroll
        for (int ni = 0; ni < 4; ++ni) {
            const int n = n0 + wn + ni * 8 + tig * 2;
            float2 v0 = { acc[mi][ni][0], acc[mi][ni][1] };
            float2 v1 = { acc[mi][ni][2], acc[mi][ni][3] };
            *(float2*)&g_x[(size_t)m * P_DIM + n]       = v0;
            *(float2*)&g_x[(size_t)(m + 8) * P_DIM + n] = v1;
        }
    }
}

// ---------------------------------------------------------------------------
// Kernel 2: per (t,p) cos/sin means over b via Chebyshev recurrence.
// Column normalization folded into the angle scale: angle = x * (dt*inv[p]).
// Fused deterministic final reduction via last-block counter.
// ---------------------------------------------------------------------------
__global__ __launch_bounds__(128) void trig_kernel(float* __restrict__ out)
{
    const int t = blockIdx.y;
    const int p = blockIdx.x * 128 + threadIdx.x;
    const float dt = 3.0f / 16.0f;
    const float sc = dt * g_inv[p];

    float ca[KNOTS - 1];
    float sa[KNOTS - 1];
    #pragma unroll
    for (int k = 0; k < KNOTS - 1; ++k) { ca[k] = 0.f; sa[k] = 0.f; }

    const float* xp = g_x + (size_t)(t * B_DIM) * P_DIM + p;
    #pragma unroll 4
    for (int b = 0; b < B_DIM; ++b) {
        float x = xp[(size_t)b * P_DIM];
        float s1, c1;
        __sincosf(x * sc, &s1, &c1);
        float ckm = 1.f, skm = 0.f;
        float ck = c1, sk = s1;
        const float tc = 2.f * c1;
        #pragma unroll
        for (int k = 1; k <= 16; ++k) {
            ca[k - 1] += ck;
            sa[k - 1] += sk;
            float cn = tc * ck - ckm;
            float sn = tc * sk - skm;
            ckm = ck; skm = sk; ck = cn; sk = sn;
        }
    }

    float val = 0.f;
    const float invB = 1.f / (float)B_DIM;
    #pragma unroll
    for (int k = 1; k <= 16; ++k) {
        float tk   = (float)k * dt;
        float phik = expf(-0.5f * tk * tk);
        float wk   = ((k == 16) ? dt : 2.f * dt) * phik;
        float cm = ca[k - 1] * invB - phik;
        float sm = sa[k - 1] * invB;
        val += wk * (cm * cm + sm * sm);
    }
    val *= (float)B_DIM;

    __shared__ float red[128];
    red[threadIdx.x] = val;
    __syncthreads();
    #pragma unroll
    for (int s = 64; s > 0; s >>= 1) {
        if (threadIdx.x < s) red[threadIdx.x] += red[threadIdx.x + s];
        __syncthreads();
    }

    __shared__ int is_last;
    if (threadIdx.x == 0) {
        g_partial[blockIdx.y * gridDim.x + blockIdx.x] = red[0];
        __threadfence();
        int prev = atomicAdd(&g_count, 1);
        is_last = (prev == (int)(gridDim.x * gridDim.y) - 1);
    }
    __syncthreads();

    if (is_last) {
        float v = g_partial[threadIdx.x] + g_partial[threadIdx.x + 128];
        red[threadIdx.x] = v;
        __syncthreads();
        #pragma unroll
        for (int s = 64; s > 0; s >>= 1) {
            if (threadIdx.x < s) red[threadIdx.x] += red[threadIdx.x + s];
            __syncthreads();
        }
        if (threadIdx.x == 0) {
            out[0] = red[0] * (1.0f / (float)(T_DIM * P_DIM));
            g_count = 0;   // reset so graph replays are deterministic
        }
    }
}

// ---------------------------------------------------------------------------
extern "C" void kernel_launch(void* const* d_in, const int* in_sizes, int n_in,
                              void* d_out, int out_size)
{
    const float* proj = (const float*)d_in[0];   // (32,64,256)
    const float* Amat = (const float*)d_in[1];   // (256,1024)
    float* out = (float*)d_out;

    cudaFuncSetAttribute(gemm_tc, cudaFuncAttributeMaxDynamicSharedMemorySize,
                         GEMM_SMEM);

    norm_kernel<<<P_DIM / 32, 256>>>(Amat);

    dim3 g1(P_DIM / 128, M_TOT / 128);   // (8, 16)
    gemm_tc<<<g1, 256, GEMM_SMEM>>>(proj, Amat);

    dim3 g2(P_DIM / 128, T_DIM);         // (8, 32) -> 256 blocks
    trig_kernel<<<g2, 128>>>(out);
}

// round 7
// speedup vs baseline: 1.9931x; 1.0514x over previous
#include <cuda_runtime.h>
#include <cstdint>

// Problem dims
#define T_DIM 32
#define B_DIM 64
#define D_DIM 256
#define P_DIM 1024
#define M_TOT (T_DIM * B_DIM)   // 2048
#define KNOTS 17

// Scratch (static device globals — no runtime allocation)
__device__ float g_x[M_TOT * P_DIM];     // 8 MB: raw proj@A (tf32 product)
__device__ float g_inv[P_DIM];           // 1/||A_col||
__device__ float g_partial[256];
__device__ int   g_count = 0;

// ---------------------------------------------------------------------------
// Kernel 1: tf32 mma.sync GEMM.  C[2048,1024] = proj @ A  (raw, unnormalized).
// Raw f32 bits fed to the tf32 MMA (HW truncation; ample error margin).
// Blocks with by==0 additionally accumulate column sum-of-squares of A from
// the B SMEM tiles and write g_inv — no separate norm kernel.
// ---------------------------------------------------------------------------
#define ASTRIDE 68
#define BSTRIDE 136
#define CHUNKA_F (128 * ASTRIDE)            // 8704 floats
#define CHUNKB_F (64 * BSTRIDE)             // 8704 floats
#define NORM_OFF (2 * CHUNKA_F + 2 * CHUNKB_F)          // 128 floats of partials
#define GEMM_SMEM ((NORM_OFF + 128) * 4)                // 139776 B

__device__ __forceinline__ void load_chunk(
    uint32_t sb, int buf, int kt, int m0, int n0,
    const float4* __restrict__ pa, const float4* __restrict__ pb, int tid)
{
    // A tile: 128 rows (m) x 16 float4 (k)
    #pragma unroll
    for (int t = 0; t < 8; ++t) {
        int idx = t * 256 + tid;
        int row = idx >> 4;                 // 0..127
        int c   = idx & 15;                 // 0..15
        uint32_t off = (uint32_t)((buf * CHUNKA_F + row * ASTRIDE + c * 4) * 4);
        const float4* s = pa + (size_t)(m0 + row) * (D_DIM / 4) + kt * 16 + c;
        asm volatile("cp.async.cg.shared.global [%0], [%1], 16;"
                     :: "r"(sb + off), "l"(s));
    }
    // B tile: 64 rows (k=d) x 32 float4 (n=p), native Amat layout
    #pragma unroll
    for (int t = 0; t < 8; ++t) {
        int idx = t * 256 + tid;
        int row = idx >> 5;                 // 0..63
        int c   = idx & 31;                 // 0..31
        uint32_t off = (uint32_t)((2 * CHUNKA_F + buf * CHUNKB_F
                                   + row * BSTRIDE + c * 4) * 4);
        const float4* s = pb + (size_t)(kt * 64 + row) * (P_DIM / 4) + n0 / 4 + c;
        asm volatile("cp.async.cg.shared.global [%0], [%1], 16;"
                     :: "r"(sb + off), "l"(s));
    }
}

__global__ __launch_bounds__(256, 1) void gemm_tc(
    const float* __restrict__ pA, const float* __restrict__ pB)
{
    extern __shared__ float sm[];
    uint32_t sb;
    asm("{ .reg .u64 t; cvta.to.shared.u64 t, %1; cvt.u32.u64 %0, t; }"
        : "=r"(sb) : "l"(sm));

    const int tid = threadIdx.x;
    const int wid = tid >> 5;
    const int lid = tid & 31;
    const int gid = lid >> 2;      // 0..7
    const int tig = lid & 3;       // 0..3
    const int wm  = (wid >> 2) * 64;
    const int wn  = (wid & 3) * 32;
    const int m0  = blockIdx.y * 128;
    const int n0  = blockIdx.x * 128;
    const bool do_norm = (blockIdx.y == 0);
    const int ncol = tid & 127;            // column for norm accumulation
    const int nhalf = tid >> 7;            // 0/1: k-range split

    const float4* pa = (const float4*)pA;
    const float4* pb = (const float4*)pB;

    float acc[4][4][4];
    #pragma unroll
    for (int mi = 0; mi < 4; ++mi)
        #pragma unroll
        for (int ni = 0; ni < 4; ++ni)
            #pragma unroll
            for (int r = 0; r < 4; ++r) acc[mi][ni][r] = 0.f;
    float nsq = 0.f;

    load_chunk(sb, 0, 0, m0, n0, pa, pb, tid);
    asm volatile("cp.async.commit_group;" ::: "memory");

    #pragma unroll
    for (int kt = 0; kt < 4; ++kt) {
        if (kt < 3) {
            load_chunk(sb, (kt + 1) & 1, kt + 1, m0, n0, pa, pb, tid);
            asm volatile("cp.async.commit_group;" ::: "memory");
            asm volatile("cp.async.wait_group 1;" ::: "memory");
        } else {
            asm volatile("cp.async.wait_group 0;" ::: "memory");
        }
        __syncthreads();

        const int buf = kt & 1;
        const float* As = sm + buf * CHUNKA_F;
        const float* Bs = sm + 2 * CHUNKA_F + buf * CHUNKB_F;

        if (do_norm) {
            const float* np = Bs + nhalf * 32 * BSTRIDE + ncol;
            #pragma unroll
            for (int j = 0; j < 32; ++j) {
                float v = np[j * BSTRIDE];
                nsq += v * v;
            }
        }

        #pragma unroll
        for (int ks = 0; ks < 8; ++ks) {
            const int kc = ks * 8;
            uint32_t a[4][4];
            #pragma unroll
            for (int mi = 0; mi < 4; ++mi) {
                const float* ap = As + (wm + mi * 16 + gid) * ASTRIDE + kc + tig;
                a[mi][0] = __float_as_uint(ap[0]);
                a[mi][1] = __float_as_uint(ap[8 * ASTRIDE]);
                a[mi][2] = __float_as_uint(ap[4]);
                a[mi][3] = __float_as_uint(ap[8 * ASTRIDE + 4]);
            }
            uint32_t b[4][2];
            #pragma unroll
            for (int ni = 0; ni < 4; ++ni) {
                const float* bp = Bs + (kc + tig) * BSTRIDE + wn + ni * 8 + gid;
                b[ni][0] = __float_as_uint(bp[0]);
                b[ni][1] = __float_as_uint(bp[4 * BSTRIDE]);
            }
            #pragma unroll
            for (int mi = 0; mi < 4; ++mi)
                #pragma unroll
                for (int ni = 0; ni < 4; ++ni)
                    asm volatile(
                        "mma.sync.aligned.m16n8k8.row.col.f32.tf32.tf32.f32 "
                        "{%0,%1,%2,%3}, {%4,%5,%6,%7}, {%8,%9}, {%0,%1,%2,%3};"
                        : "+f"(acc[mi][ni][0]), "+f"(acc[mi][ni][1]),
                          "+f"(acc[mi][ni][2]), "+f"(acc[mi][ni][3])
                        : "r"(a[mi][0]), "r"(a[mi][1]), "r"(a[mi][2]), "r"(a[mi][3]),
                          "r"(b[ni][0]), "r"(b[ni][1]));
        }
        __syncthreads();
    }

    // Norm epilogue (by==0 blocks): combine k-halves, write g_inv
    if (do_norm) {
        if (nhalf == 1) sm[NORM_OFF + ncol] = nsq;
        __syncthreads();
        if (nhalf == 0) {
            float t = nsq + sm[NORM_OFF + ncol];
            g_inv[n0 + ncol] = 1.f / fmaxf(sqrtf(t), 1e-12f);
        }
    }

    // C epilogue
    #pragma unroll
    for (int mi = 0; mi < 4; ++mi) {
        const int m = m0 + wm + mi * 16 + gid;
        #pragma unroll
        for (int ni = 0; ni < 4; ++ni) {
            const int n = n0 + wn + ni * 8 + tig * 2;
            float2 v0 = { acc[mi][ni][0], acc[mi][ni][1] };
            float2 v1 = { acc[mi][ni][2], acc[mi][ni][3] };
            *(float2*)&g_x[(size_t)m * P_DIM + n]       = v0;
            *(float2*)&g_x[(size_t)(m + 8) * P_DIM + n] = v1;
        }
    }
}

// ---------------------------------------------------------------------------
// Kernel 2: per (t,p) cos/sin means over b via Chebyshev recurrence.
// 256 threads/block: 2 halves each handle 32 of the 64 b values (occupancy
// 2x), partial knot sums merged via SMEM.  Normalization folded into angle
// scale.  Fused deterministic final reduction via last-block counter.
// ---------------------------------------------------------------------------
__global__ __launch_bounds__(256) void trig_kernel(float* __restrict__ out)
{
    const int t  = blockIdx.y;
    const int pl = threadIdx.x & 127;
    const int hf = threadIdx.x >> 7;        // 0/1: b-range split
    const int p  = blockIdx.x * 128 + pl;
    const float dt = 3.0f / 16.0f;
    const float sc = dt * g_inv[p];

    float ca[KNOTS - 1];
    float sa[KNOTS - 1];
    #pragma unroll
    for (int k = 0; k < KNOTS - 1; ++k) { ca[k] = 0.f; sa[k] = 0.f; }

    const float* xp = g_x + (size_t)(t * B_DIM + hf * 32) * P_DIM + p;
    #pragma unroll 4
    for (int b = 0; b < 32; ++b) {
        float x = xp[(size_t)b * P_DIM];
        float s1, c1;
        __sincosf(x * sc, &s1, &c1);
        float ckm = 1.f, skm = 0.f;
        float ck = c1, sk = s1;
        const float tc = 2.f * c1;
        #pragma unroll
        for (int k = 1; k <= 16; ++k) {
            ca[k - 1] += ck;
            sa[k - 1] += sk;
            float cn = tc * ck - ckm;
            float sn = tc * sk - skm;
            ckm = ck; skm = sk; ck = cn; sk = sn;
        }
    }

    // Merge half 1 into half 0 via SMEM
    __shared__ float mc[KNOTS - 1][128];
    __shared__ float ms[KNOTS - 1][128];
    if (hf == 1) {
        #pragma unroll
        for (int k = 0; k < KNOTS - 1; ++k) { mc[k][pl] = ca[k]; ms[k][pl] = sa[k]; }
    }
    __syncthreads();

    float val = 0.f;
    if (hf == 0) {
        const float invB = 1.f / (float)B_DIM;
        #pragma unroll
        for (int k = 1; k <= 16; ++k) {
            float tk   = (float)k * dt;
            float phik = expf(-0.5f * tk * tk);
            float wk   = ((k == 16) ? dt : 2.f * dt) * phik;
            float cm = (ca[k - 1] + mc[k - 1][pl]) * invB - phik;
            float sm = (sa[k - 1] + ms[k - 1][pl]) * invB;
            val += wk * (cm * cm + sm * sm);
        }
        val *= (float)B_DIM;
    }

    __shared__ float red[256];
    red[threadIdx.x] = val;
    __syncthreads();
    #pragma unroll
    for (int s = 128; s > 0; s >>= 1) {
        if (threadIdx.x < s) red[threadIdx.x] += red[threadIdx.x + s];
        __syncthreads();
    }

    __shared__ int is_last;
    if (threadIdx.x == 0) {
        g_partial[blockIdx.y * gridDim.x + blockIdx.x] = red[0];
        __threadfence();
        int prev = atomicAdd(&g_count, 1);
        is_last = (prev == (int)(gridDim.x * gridDim.y) - 1);
    }
    __syncthreads();

    if (is_last) {
        red[threadIdx.x] = g_partial[threadIdx.x];
        __syncthreads();
        #pragma unroll
        for (int s = 128; s > 0; s >>= 1) {
            if (threadIdx.x < s) red[threadIdx.x] += red[threadIdx.x + s];
            __syncthreads();
        }
        if (threadIdx.x == 0) {
            out[0] = red[0] * (1.0f / (float)(T_DIM * P_DIM));
            g_count = 0;   // reset so graph replays are deterministic
        }
    }
}

// ---------------------------------------------------------------------------
extern "C" void kernel_launch(void* const* d_in, const int* in_sizes, int n_in,
                              void* d_out, int out_size)
{
    const float* proj = (const float*)d_in[0];   // (32,64,256)
    const float* Amat = (const float*)d_in[1];   // (256,1024)
    float* out = (float*)d_out;

    cudaFuncSetAttribute(gemm_tc, cudaFuncAttributeMaxDynamicSharedMemorySize,
                         GEMM_SMEM);

    dim3 g1(P_DIM / 128, M_TOT / 128);   // (8, 16)
    gemm_tc<<<g1, 256, GEMM_SMEM>>>(proj, Amat);

    dim3 g2(P_DIM / 128, T_DIM);         // (8, 32) -> 256 blocks
    trig_kernel<<<g2, 256>>>(out);
}

// round 8
// speedup vs baseline: 2.2245x; 1.1161x over previous
#include <cuda_runtime.h>
#include <cstdint>

// Problem dims
#define T_DIM 32
#define B_DIM 64
#define D_DIM 256
#define P_DIM 1024
#define M_TOT (T_DIM * B_DIM)   // 2048
#define KNOTS 17

// Scratch (static device globals — no runtime allocation)
__device__ float g_x[M_TOT * P_DIM];     // 8 MB: raw proj@A (tf32 product)
__device__ float g_inv[P_DIM];           // 1/||A_col||
__device__ float g_partial[256];
__device__ int   g_count = 0;

// RNA(f32 -> tf32) == truncate(bits + 0x1000); the MMA input converter
// truncates, so one IADD on the bits gives exact round-to-nearest-away.
#define RNA_BIAS 0x1000u

// ---------------------------------------------------------------------------
// Kernel 1: tf32 mma.sync GEMM.  C[2048,1024] = proj @ A  (raw, unnormalized).
// Fragment bits get +0x1000 (ALU pipe, hidden under HMMA) -> RNA rounding.
// Blocks with by==0 also accumulate column sum-of-squares of A from the B
// SMEM tiles and write g_inv — no separate norm kernel.
// ---------------------------------------------------------------------------
#define ASTRIDE 68
#define BSTRIDE 136
#define CHUNKA_F (128 * ASTRIDE)            // 8704 floats
#define CHUNKB_F (64 * BSTRIDE)             // 8704 floats
#define NORM_OFF (2 * CHUNKA_F + 2 * CHUNKB_F)          // 128 floats of partials
#define GEMM_SMEM ((NORM_OFF + 128) * 4)                // 139776 B

__device__ __forceinline__ void load_chunk(
    uint32_t sb, int buf, int kt, int m0, int n0,
    const float4* __restrict__ pa, const float4* __restrict__ pb, int tid)
{
    // A tile: 128 rows (m) x 16 float4 (k)
    #pragma unroll
    for (int t = 0; t < 8; ++t) {
        int idx = t * 256 + tid;
        int row = idx >> 4;                 // 0..127
        int c   = idx & 15;                 // 0..15
        uint32_t off = (uint32_t)((buf * CHUNKA_F + row * ASTRIDE + c * 4) * 4);
        const float4* s = pa + (size_t)(m0 + row) * (D_DIM / 4) + kt * 16 + c;
        asm volatile("cp.async.cg.shared.global [%0], [%1], 16;"
                     :: "r"(sb + off), "l"(s));
    }
    // B tile: 64 rows (k=d) x 32 float4 (n=p), native Amat layout
    #pragma unroll
    for (int t = 0; t < 8; ++t) {
        int idx = t * 256 + tid;
        int row = idx >> 5;                 // 0..63
        int c   = idx & 31;                 // 0..31
        uint32_t off = (uint32_t)((2 * CHUNKA_F + buf * CHUNKB_F
                                   + row * BSTRIDE + c * 4) * 4);
        const float4* s = pb + (size_t)(kt * 64 + row) * (P_DIM / 4) + n0 / 4 + c;
        asm volatile("cp.async.cg.shared.global [%0], [%1], 16;"
                     :: "r"(sb + off), "l"(s));
    }
}

__global__ __launch_bounds__(256, 1) void gemm_tc(
    const float* __restrict__ pA, const float* __restrict__ pB)
{
    extern __shared__ float sm[];
    uint32_t sb;
    asm("{ .reg .u64 t; cvta.to.shared.u64 t, %1; cvt.u32.u64 %0, t; }"
        : "=r"(sb) : "l"(sm));

    const int tid = threadIdx.x;
    const int wid = tid >> 5;
    const int lid = tid & 31;
    const int gid = lid >> 2;      // 0..7
    const int tig = lid & 3;       // 0..3
    const int wm  = (wid >> 2) * 64;
    const int wn  = (wid & 3) * 32;
    const int m0  = blockIdx.y * 128;
    const int n0  = blockIdx.x * 128;
    const bool do_norm = (blockIdx.y == 0);
    const int ncol = tid & 127;            // column for norm accumulation
    const int nhalf = tid >> 7;            // 0/1: k-range split

    const float4* pa = (const float4*)pA;
    const float4* pb = (const float4*)pB;

    float acc[4][4][4];
    #pragma unroll
    for (int mi = 0; mi < 4; ++mi)
        #pragma unroll
        for (int ni = 0; ni < 4; ++ni)
            #pragma unroll
            for (int r = 0; r < 4; ++r) acc[mi][ni][r] = 0.f;
    float nsq = 0.f;

    load_chunk(sb, 0, 0, m0, n0, pa, pb, tid);
    asm volatile("cp.async.commit_group;" ::: "memory");

    #pragma unroll
    for (int kt = 0; kt < 4; ++kt) {
        if (kt < 3) {
            load_chunk(sb, (kt + 1) & 1, kt + 1, m0, n0, pa, pb, tid);
            asm volatile("cp.async.commit_group;" ::: "memory");
            asm volatile("cp.async.wait_group 1;" ::: "memory");
        } else {
            asm volatile("cp.async.wait_group 0;" ::: "memory");
        }
        __syncthreads();

        const int buf = kt & 1;
        const float* As = sm + buf * CHUNKA_F;
        const float* Bs = sm + 2 * CHUNKA_F + buf * CHUNKB_F;

        if (do_norm) {
            const float* np = Bs + nhalf * 32 * BSTRIDE + ncol;
            #pragma unroll
            for (int j = 0; j < 32; ++j) {
                float v = np[j * BSTRIDE];
                nsq += v * v;
            }
        }

        #pragma unroll
        for (int ks = 0; ks < 8; ++ks) {
            const int kc = ks * 8;
            uint32_t a[4][4];
            #pragma unroll
            for (int mi = 0; mi < 4; ++mi) {
                const float* ap = As + (wm + mi * 16 + gid) * ASTRIDE + kc + tig;
                a[mi][0] = __float_as_uint(ap[0])              + RNA_BIAS;
                a[mi][1] = __float_as_uint(ap[8 * ASTRIDE])    + RNA_BIAS;
                a[mi][2] = __float_as_uint(ap[4])              + RNA_BIAS;
                a[mi][3] = __float_as_uint(ap[8 * ASTRIDE + 4]) + RNA_BIAS;
            }
            uint32_t b[4][2];
            #pragma unroll
            for (int ni = 0; ni < 4; ++ni) {
                const float* bp = Bs + (kc + tig) * BSTRIDE + wn + ni * 8 + gid;
                b[ni][0] = __float_as_uint(bp[0])              + RNA_BIAS;
                b[ni][1] = __float_as_uint(bp[4 * BSTRIDE])    + RNA_BIAS;
            }
            #pragma unroll
            for (int mi = 0; mi < 4; ++mi)
                #pragma unroll
                for (int ni = 0; ni < 4; ++ni)
                    asm volatile(
                        "mma.sync.aligned.m16n8k8.row.col.f32.tf32.tf32.f32 "
                        "{%0,%1,%2,%3}, {%4,%5,%6,%7}, {%8,%9}, {%0,%1,%2,%3};"
                        : "+f"(acc[mi][ni][0]), "+f"(acc[mi][ni][1]),
                          "+f"(acc[mi][ni][2]), "+f"(acc[mi][ni][3])
                        : "r"(a[mi][0]), "r"(a[mi][1]), "r"(a[mi][2]), "r"(a[mi][3]),
                          "r"(b[ni][0]), "r"(b[ni][1]));
        }
        __syncthreads();
    }

    // Norm epilogue (by==0 blocks): combine k-halves, write g_inv
    if (do_norm) {
        if (nhalf == 1) sm[NORM_OFF + ncol] = nsq;
        __syncthreads();
        if (nhalf == 0) {
            float t = nsq + sm[NORM_OFF + ncol];
            g_inv[n0 + ncol] = 1.f / fmaxf(sqrtf(t), 1e-12f);
        }
    }

    // C epilogue
    #pragma unroll
    for (int mi = 0; mi < 4; ++mi) {
        const int m = m0 + wm + mi * 16 + gid;
        #pragma unroll
        for (int ni = 0; ni < 4; ++ni) {
            const int n = n0 + wn + ni * 8 + tig * 2;
            float2 v0 = { acc[mi][ni][0], acc[mi][ni][1] };
            float2 v1 = { acc[mi][ni][2], acc[mi][ni][3] };
            *(float2*)&g_x[(size_t)m * P_DIM + n]       = v0;
            *(float2*)&g_x[(size_t)(m + 8) * P_DIM + n] = v1;
        }
    }
}

// ---------------------------------------------------------------------------
// Kernel 2: per (t,p) cos/sin means over b via Chebyshev recurrence.
// 512 threads/block: FOUR b-quarters (16 b each) -> 4096 warps chip-wide,
// hiding the 16-step serial FMA chain.  Quarter partial knot-sums merged via
// SMEM.  Normalization folded into angle scale.  Fused deterministic final
// reduction via last-block counter.
// ---------------------------------------------------------------------------
__global__ __launch_bounds__(512) void trig_kernel(float* __restrict__ out)
{
    const int t  = blockIdx.y;
    const int pl = threadIdx.x & 127;
    const int qt = threadIdx.x >> 7;        // 0..3: b-quarter
    const int p  = blockIdx.x * 128 + pl;
    const float dt = 3.0f / 16.0f;
    const float sc = dt * g_inv[p];

    float ca[KNOTS - 1];
    float sa[KNOTS - 1];
    #pragma unroll
    for (int k = 0; k < KNOTS - 1; ++k) { ca[k] = 0.f; sa[k] = 0.f; }

    const float* xp = g_x + (size_t)(t * B_DIM + qt * 16) * P_DIM + p;
    #pragma unroll 4
    for (int b = 0; b < 16; ++b) {
        float x = xp[(size_t)b * P_DIM];
        float s1, c1;
        __sincosf(x * sc, &s1, &c1);
        float ckm = 1.f, skm = 0.f;
        float ck = c1, sk = s1;
        const float tc = 2.f * c1;
        #pragma unroll
        for (int k = 1; k <= 16; ++k) {
            ca[k - 1] += ck;
            sa[k - 1] += sk;
            float cn = tc * ck - ckm;
            float sn = tc * sk - skm;
            ckm = ck; skm = sk; ck = cn; sk = sn;
        }
    }

    // Merge quarters 1..3 into quarter 0 via SMEM (48 KB)
    __shared__ float mc[3][KNOTS - 1][128];
    __shared__ float ms[3][KNOTS - 1][128];
    if (qt > 0) {
        #pragma unroll
        for (int k = 0; k < KNOTS - 1; ++k) {
            mc[qt - 1][k][pl] = ca[k];
            ms[qt - 1][k][pl] = sa[k];
        }
    }
    __syncthreads();

    float val = 0.f;
    if (qt == 0) {
        const float invB = 1.f / (float)B_DIM;
        #pragma unroll
        for (int k = 1; k <= 16; ++k) {
            float tk   = (float)k * dt;
            float phik = expf(-0.5f * tk * tk);
            float wk   = ((k == 16) ? dt : 2.f * dt) * phik;
            float cs = ca[k - 1] + mc[0][k - 1][pl] + mc[1][k - 1][pl] + mc[2][k - 1][pl];
            float ss = sa[k - 1] + ms[0][k - 1][pl] + ms[1][k - 1][pl] + ms[2][k - 1][pl];
            float cm = cs * invB - phik;
            float smn = ss * invB;
            val += wk * (cm * cm + smn * smn);
        }
        val *= (float)B_DIM;
    }

    __shared__ float red[512];
    red[threadIdx.x] = val;
    __syncthreads();
    #pragma unroll
    for (int s = 256; s > 0; s >>= 1) {
        if (threadIdx.x < s) red[threadIdx.x] += red[threadIdx.x + s];
        __syncthreads();
    }

    __shared__ int is_last;
    if (threadIdx.x == 0) {
        g_partial[blockIdx.y * gridDim.x + blockIdx.x] = red[0];
        __threadfence();
        int prev = atomicAdd(&g_count, 1);
        is_last = (prev == (int)(gridDim.x * gridDim.y) - 1);
    }
    __syncthreads();

    if (is_last) {
        float v = (threadIdx.x < 256) ? g_partial[threadIdx.x] : 0.f;
        red[threadIdx.x] = v;
        __syncthreads();
        #pragma unroll
        for (int s = 256; s > 0; s >>= 1) {
            if (threadIdx.x < s) red[threadIdx.x] += red[threadIdx.x + s];
            __syncthreads();
        }
        if (threadIdx.x == 0) {
            out[0] = red[0] * (1.0f / (float)(T_DIM * P_DIM));
            g_count = 0;   // reset so graph replays are deterministic
        }
    }
}

// ---------------------------------------------------------------------------
extern "C" void kernel_launch(void* const* d_in, const int* in_sizes, int n_in,
                              void* d_out, int out_size)
{
    const float* proj = (const float*)d_in[0];   // (32,64,256)
    const float* Amat = (const float*)d_in[1];   // (256,1024)
    float* out = (float*)d_out;

    cudaFuncSetAttribute(gemm_tc, cudaFuncAttributeMaxDynamicSharedMemorySize,
                         GEMM_SMEM);

    dim3 g1(P_DIM / 128, M_TOT / 128);   // (8, 16)
    gemm_tc<<<g1, 256, GEMM_SMEM>>>(proj, Amat);

    dim3 g2(P_DIM / 128, T_DIM);         // (8, 32) -> 256 blocks
    trig_kernel<<<g2, 512>>>(out);
}